// round 3
// baseline (speedup 1.0000x reference)
#include <cuda_runtime.h>

// Problem constants (fixed by setup_inputs)
#define BB 8
#define NN 32
#define CC 80
#define NBC (BB * CC)   // 640 (batch, class) channels

// Per-channel loss scratch (written every launch before being read; no init needed)
__device__ float g_loss[NBC];

__device__ __forceinline__ float warp_sum(float v) {
#pragma unroll
    for (int o = 16; o > 0; o >>= 1) v += __shfl_down_sync(0xffffffffu, v, o);
    return v;
}

// One block per (b, c). Processes the 3 pyramid levels (128^2 + 64^2 + 32^2 pixels),
// computing the gaussian target on the fly from the (rare) boxes whose label == c.
__global__ __launch_bounds__(256) void hough_loss_kernel(
    const float* __restrict__ h0, const float* __restrict__ h1,
    const float* __restrict__ h2, const float* __restrict__ boxes,
    const int* __restrict__ labels)
{
    const int bc  = blockIdx.x;
    const int b   = bc / CC;
    const int c   = bc % CC;
    const int tid = threadIdx.x;

    __shared__ int   s_nb;
    __shared__ int   s_x[NN], s_y[NN], s_r[NN];
    __shared__ float s_inv[NN];
    __shared__ float s_red[3][8];

    float pl = 0.f, nl = 0.f, npos = 0.f;

    const float* heats[3] = {h0, h1, h2};

#pragma unroll
    for (int lvl = 0; lvl < 3; ++lvl) {
        const int W  = 128 >> lvl;
        const int HW = W * W;

        // Filter this batch's boxes for label == c and precompute per-level params.
        if (tid == 0) s_nb = 0;
        __syncthreads();
        if (tid < NN && labels[b * NN + tid] == c) {
            const float* bp = boxes + ((size_t)b * NN + tid) * 4;
            const float fW = (float)W;
            int x = (int)floorf(bp[0] * fW);          // floor of positive value == int trunc
            int y = (int)floorf(bp[1] * fW);
            float bw = bp[2] * fW, bh = bp[3] * fW;
            int r = (int)floorf((bw + bh) * 0.25f);
            if (r < 1) r = 1;
            float sigma = (float)(2 * r + 1) * (1.0f / 6.0f);
            float inv   = 1.0f / (2.0f * sigma * sigma);
            int i = atomicAdd(&s_nb, 1);
            s_x[i] = x; s_y[i] = y; s_r[i] = r; s_inv[i] = inv;
        }
        __syncthreads();
        const int nb = s_nb;
        const float* __restrict__ heat = heats[lvl] + (size_t)bc * HW;
        const int sh = 7 - lvl;  // idx / W  ==  idx >> sh  (W is a power of two)

        for (int idx = tid; idx < HW; idx += 256) {
            const int y = idx >> sh;
            const int x = idx & (W - 1);
            const float h = heat[idx];

            // target = max over matching boxes of windowed gaussian (0 if none).
            float t = 0.f;
            for (int i = 0; i < nb; ++i) {
                int dx = x - s_x[i];
                int dy = y - s_y[i];
                int r  = s_r[i];
                // |dx|<=r && |dy|<=r  via unsigned range trick
                if ((unsigned)(dx + r) <= (unsigned)(2 * r) &&
                    (unsigned)(dy + r) <= (unsigned)(2 * r)) {
                    float g = __expf((float)(dx * dx + dy * dy) * -s_inv[i]);
                    t = fmaxf(t, g);
                }
            }

            float p = 1.0f / (1.0f + __expf(-h));
            p = fminf(fmaxf(p, 1e-4f), 1.0f - 1e-4f);

            if (t == 1.0f) {                 // exact: only d2==0 yields 1.0f
                float q = 1.0f - p;
                pl += __logf(p) * q * q;
                npos += 1.0f;
            } else {
                float u  = 1.0f - t;
                float u2 = u * u;
                nl += __logf(1.0f - p) * (p * p) * (u2 * u2);
            }
        }
        __syncthreads();  // protect smem box list before next level overwrites it
    }

    // Deterministic block reduction of (pl, nl, npos)
    pl = warp_sum(pl); nl = warp_sum(nl); npos = warp_sum(npos);
    const int wid = tid >> 5, lane = tid & 31;
    if (lane == 0) { s_red[0][wid] = pl; s_red[1][wid] = nl; s_red[2][wid] = npos; }
    __syncthreads();
    if (tid == 0) {
        float P = 0.f, Nl = 0.f, Np = 0.f;
#pragma unroll
        for (int w = 0; w < 8; ++w) { P += s_red[0][w]; Nl += s_red[1][w]; Np += s_red[2][w]; }
        float loss = (Np == 0.f) ? -Nl : -((P + Nl) / Np);
        loss = fminf(loss, 10.0f);
        g_loss[bc] = loss;
    }
}

// Deterministic final reduction: mean over 640 channel losses -> log1p squash.
__global__ __launch_bounds__(256) void hough_finalize(float* __restrict__ out) {
    __shared__ float s_red[8];
    const int tid = threadIdx.x;
    float s = 0.f;
    for (int i = tid; i < NBC; i += 256) s += g_loss[i];
    s = warp_sum(s);
    if ((tid & 31) == 0) s_red[tid >> 5] = s;
    __syncthreads();
    if (tid == 0) {
        float tot = 0.f;
#pragma unroll
        for (int w = 0; w < 8; ++w) tot += s_red[w];
        float mean = tot * (1.0f / (float)NBC);
        float lm = log1pf(mean);
        out[0] = lm / (1.0f + lm);
    }
}

extern "C" void kernel_launch(void* const* d_in, const int* in_sizes, int n_in,
                              void* d_out, int out_size) {
    const float* h0     = (const float*)d_in[0];  // [8,80,128,128]
    const float* h1     = (const float*)d_in[1];  // [8,80,64,64]
    const float* h2     = (const float*)d_in[2];  // [8,80,32,32]
    const float* boxes  = (const float*)d_in[3];  // [8,32,4]
    const int*   labels = (const int*)d_in[4];    // [8,32]
    // d_in[5] (image_sizes) cancels out in the reference math.

    hough_loss_kernel<<<NBC, 256>>>(h0, h1, h2, boxes, labels);
    hough_finalize<<<1, 256>>>((float*)d_out);
}

// round 4
// speedup vs baseline: 2.0039x; 2.0039x over previous
#include <cuda_runtime.h>

// Problem constants (fixed by setup_inputs)
#define BB 8
#define NN 32
#define CC 80
#define NBC (BB * CC)        // 640 (batch,class) channels
#define NSLOT 6              // per-channel partial slots: 4 L0 tiles + L1 + L2
#define NBLK (NBC * NSLOT)   // 3840 blocks

// Per-block partial sums (all written every launch before finalize reads them)
__device__ float g_pl[NBLK];
__device__ float g_nl[NBLK];
__device__ float g_np[NBLK];

__device__ __forceinline__ float warp_sum(float v) {
#pragma unroll
    for (int o = 16; o > 0; o >>= 1) v += __shfl_down_sync(0xffffffffu, v, o);
    return v;
}

// Balanced grid: bid < 2560 -> level0 (ch = bid>>2, 4096-px tile = bid&3)
//                bid < 3200 -> level1 (4096 px), else level2 (1024 px).
__global__ __launch_bounds__(256) void hough_main(
    const float* __restrict__ h0, const float* __restrict__ h1,
    const float* __restrict__ h2, const float* __restrict__ boxes,
    const int* __restrict__ labels)
{
    const int bid = blockIdx.x;
    const int tid = threadIdx.x;

    int lvl, ch, tile, slot;
    if (bid < 2560)      { lvl = 0; ch = bid >> 2;   tile = bid & 3; slot = tile; }
    else if (bid < 3200) { lvl = 1; ch = bid - 2560; tile = 0;       slot = 4; }
    else                 { lvl = 2; ch = bid - 3200; tile = 0;       slot = 5; }

    const int W    = 128 >> lvl;
    const int sh   = 7 - lvl;
    const int npx  = (lvl == 2) ? 1024 : 4096;
    const int poff = tile * 4096;      // pixel offset within this channel's map

    const float* heat;
    if (lvl == 0)      heat = h0 + (size_t)ch * 16384 + poff;
    else if (lvl == 1) heat = h1 + (size_t)ch * 4096;
    else               heat = h2 + (size_t)ch * 1024;

    const int b = ch / CC;
    const int c = ch % CC;

    __shared__ int   s_nb;
    __shared__ int   s_x[NN], s_y[NN], s_r[NN];
    __shared__ float s_inv[NN];
    __shared__ float s_red[3][8];

    // Filter this batch's boxes: label match + row-window intersects this tile.
    if (tid == 0) s_nb = 0;
    __syncthreads();
    if (tid < NN && labels[b * NN + tid] == c) {
        const float* bp = boxes + ((size_t)b * NN + tid) * 4;
        const float fW = (float)W;
        int x = (int)floorf(bp[0] * fW);          // positive -> floor == trunc
        int y = (int)floorf(bp[1] * fW);
        float bw = bp[2] * fW, bh = bp[3] * fW;
        int r = (int)floorf((bw + bh) * 0.25f);
        if (r < 1) r = 1;
        const int y0 = poff >> sh;                     // first row this block covers
        const int y1 = ((poff + npx) >> sh) - 1;       // last row
        if (y + r >= y0 && y - r <= y1) {
            float sg  = (float)(2 * r + 1) * (1.0f / 6.0f);
            float inv = 1.0f / (2.0f * sg * sg);
            int i = atomicAdd(&s_nb, 1);
            s_x[i] = x; s_y[i] = y; s_r[i] = r; s_inv[i] = inv;
        }
    }
    __syncthreads();
    const int nb = s_nb;

    float pl = 0.f, nl = 0.f, np = 0.f;
    const int nvec = npx >> 2;
    const float4* __restrict__ hv4 = (const float4*)heat;

    // Focal-loss core with 3 MUFU total:
    //   E = e^-h;  R = 1/(1+E) = p;  L = ln(1+E)
    //   ln p = -L;  1-p = E*R;  ln(1-p) = -h - L
    if (nb == 0) {
        // No boxes: t == 0 everywhere -> pure negative loss, (1-t)^4 == 1.
        for (int i = tid; i < nvec; i += 256) {
            float4 hv = hv4[i];
            float hs[4] = {hv.x, hv.y, hv.z, hv.w};
#pragma unroll
            for (int j = 0; j < 4; ++j) {
                float h = hs[j];
                float E = __expf(-h);
                float S = 1.0f + E;
                float R = __fdividef(1.0f, S);
                float L = __logf(S);
                nl += (-h - L) * R * R;
            }
        }
    } else {
        for (int i = tid; i < nvec; i += 256) {
            float4 hv = hv4[i];
            const int p0 = poff + i * 4;
            const int y  = p0 >> sh;
            const int x0 = p0 & (W - 1);          // 4 consecutive x in one row
            float hs[4] = {hv.x, hv.y, hv.z, hv.w};
#pragma unroll
            for (int j = 0; j < 4; ++j) {
                float h = hs[j];
                const int x = x0 + j;

                float t = 0.f;
                for (int k = 0; k < nb; ++k) {
                    int dx = x - s_x[k];
                    int dy = y - s_y[k];
                    int r  = s_r[k];
                    if ((unsigned)(dx + r) <= (unsigned)(2 * r) &&
                        (unsigned)(dy + r) <= (unsigned)(2 * r)) {
                        float g = __expf((float)(dx * dx + dy * dy) * -s_inv[k]);
                        t = fmaxf(t, g);
                    }
                }

                float E = __expf(-h);
                float S = 1.0f + E;
                float R = __fdividef(1.0f, S);
                float L = __logf(S);

                const bool pos = (t == 1.0f);     // exact: only d2==0 gives 1.0f
                float u  = 1.0f - t;
                float u2 = u * u;
                float ER = E * R;
                float posterm = -L * ER * ER;                  // ln(p)(1-p)^2
                float negterm = (-h - L) * R * R * (u2 * u2);  // ln(1-p) p^2 (1-t)^4
                pl += pos ? posterm : 0.f;
                nl += pos ? 0.f : negterm;
                np += pos ? 1.f : 0.f;
            }
        }
    }

    // Deterministic block reduction
    pl = warp_sum(pl); nl = warp_sum(nl); np = warp_sum(np);
    const int wid = tid >> 5, lane = tid & 31;
    if (lane == 0) { s_red[0][wid] = pl; s_red[1][wid] = nl; s_red[2][wid] = np; }
    __syncthreads();
    if (tid == 0) {
        float P = 0.f, Nl = 0.f, Np = 0.f;
#pragma unroll
        for (int w = 0; w < 8; ++w) { P += s_red[0][w]; Nl += s_red[1][w]; Np += s_red[2][w]; }
        const int o = ch * NSLOT + slot;
        g_pl[o] = P; g_nl[o] = Nl; g_np[o] = Np;
    }
}

// Deterministic finalize: per-channel combine of 6 partials -> loss -> mean -> squash.
__global__ __launch_bounds__(NBC) void hough_finalize(float* __restrict__ out) {
    __shared__ float s_red[NBC / 32];
    const int tid = threadIdx.x;   // 640 threads, one per channel

    float P = 0.f, Nl = 0.f, Np = 0.f;
#pragma unroll
    for (int s = 0; s < NSLOT; ++s) {
        const int o = tid * NSLOT + s;
        P += g_pl[o]; Nl += g_nl[o]; Np += g_np[o];
    }
    float loss = (Np == 0.f) ? -Nl : -((P + Nl) / Np);
    loss = fminf(loss, 10.0f);

    loss = warp_sum(loss);
    if ((tid & 31) == 0) s_red[tid >> 5] = loss;
    __syncthreads();
    if (tid == 0) {
        float tot = 0.f;
#pragma unroll
        for (int w = 0; w < NBC / 32; ++w) tot += s_red[w];
        float mean = tot * (1.0f / (float)NBC);
        float lm = log1pf(mean);
        out[0] = lm / (1.0f + lm);
    }
}

extern "C" void kernel_launch(void* const* d_in, const int* in_sizes, int n_in,
                              void* d_out, int out_size) {
    const float* h0     = (const float*)d_in[0];  // [8,80,128,128]
    const float* h1     = (const float*)d_in[1];  // [8,80,64,64]
    const float* h2     = (const float*)d_in[2];  // [8,80,32,32]
    const float* boxes  = (const float*)d_in[3];  // [8,32,4]
    const int*   labels = (const int*)d_in[4];    // [8,32]
    // d_in[5] (image_sizes) cancels out in the reference math.

    hough_main<<<NBLK, 256>>>(h0, h1, h2, boxes, labels);
    hough_finalize<<<1, NBC>>>((float*)d_out);
}